// round 4
// baseline (speedup 1.0000x reference)
#include <cuda_runtime.h>
#include <cstdint>

#define MM 1024
#define NN 4096
#define TCAND 4
#define FULLMASK 0xffffffffu

typedef unsigned int       u32;
typedef unsigned long long u64;

// ---------------- device scratch (no allocations allowed) ----------------
__device__ int   g_colhit[NN];
__device__ u32   g_colbits[NN / 32];
__device__ float g_rowmax[MM];
__device__ float g_rowsum[MM];
__device__ u64   g_cand[MM * TCAND];   // per-row top-4: key<<32 | col
__device__ float g_gmax;
__device__ float g_gsum;

// Monotonic float -> uint32 ordering key (nonzero for all real floats).
__device__ __forceinline__ u32 orderKey(float v) {
    u32 b = __float_as_uint(v);
    return (b & 0x80000000u) ? ~b : (b | 0x80000000u);
}

// Packed head: key high, inverted flat index (row<<12|col) low 23 bits.
// u64 max == (max key, then smallest flat index) — exact reference tie-break.
__device__ __forceinline__ u64 packHead(u32 key, u32 rc) {
    return ((u64)key << 23) | (u64)(0x400000u - rc);
}

// ---------------- K0: column-hit mask (bytes + bitmask) ------------------
__global__ void k0_colhit(const int* __restrict__ cont, const int* __restrict__ prev) {
    int tid = threadIdx.x;                 // 1024 threads
    #pragma unroll
    for (int k = 0; k < 4; k++) g_colhit[tid + k * 1024] = 0;
    if (tid < NN / 32) g_colbits[tid] = 0;
    __syncthreads();
    if (cont[tid]) {
        int c = prev[tid];
        g_colhit[c] = 1;                                  // benign races
        atomicOr(&g_colbits[c >> 5], 1u << (c & 31));
    }
}

// ---------------- K1: per-row rowmax, sumexp, top-4 masked candidates ----
__global__ void __launch_bounds__(256) k1_row(const float* __restrict__ scores,
                                              const int* __restrict__ cont) {
    const int r = blockIdx.x, tid = threadIdx.x, lane = tid & 31, warp = tid >> 5;
    __shared__ float wf[8];
    __shared__ u32   wk[8], wc[8];
    __shared__ float s_bcast;
    __shared__ u32   s_wincol;

    const float4* row = (const float4*)(scores + (size_t)r * NN);
    const bool isCont = (cont[r] != 0);

    float vals[16];
    int   fidx[4];
    #pragma unroll
    for (int k = 0; k < 4; k++) {
        int f = tid + k * 256; fidx[k] = f;
        float4 v = row[f];
        vals[k * 4 + 0] = v.x; vals[k * 4 + 1] = v.y;
        vals[k * 4 + 2] = v.z; vals[k * 4 + 3] = v.w;
    }
    u32 freeMask = 0;
    if (!isCont) {
        #pragma unroll
        for (int k = 0; k < 4; k++) {
            int4 h = ((const int4*)g_colhit)[fidx[k]];
            if (!h.x) freeMask |= 1u << (k * 4 + 0);
            if (!h.y) freeMask |= 1u << (k * 4 + 1);
            if (!h.z) freeMask |= 1u << (k * 4 + 2);
            if (!h.w) freeMask |= 1u << (k * 4 + 3);
        }
    }

    // ---- raw row max ----
    float m = vals[0];
    #pragma unroll
    for (int e = 1; e < 16; e++) m = fmaxf(m, vals[e]);
    #pragma unroll
    for (int off = 16; off; off >>= 1) m = fmaxf(m, __shfl_xor_sync(FULLMASK, m, off));
    if (lane == 0) wf[warp] = m;
    __syncthreads();
    if (warp == 0) {
        float t = (lane < 8) ? wf[lane] : -3.4e38f;
        #pragma unroll
        for (int off = 4; off; off >>= 1) t = fmaxf(t, __shfl_xor_sync(FULLMASK, t, off));
        if (lane == 0) { s_bcast = t; g_rowmax[r] = t; }
    }
    __syncthreads();
    float rowmax = s_bcast;

    // ---- row sumexp (stable at rowmax) ----
    float s = 0.f;
    #pragma unroll
    for (int e = 0; e < 16; e++) s += __expf(vals[e] - rowmax);
    #pragma unroll
    for (int off = 16; off; off >>= 1) s += __shfl_xor_sync(FULLMASK, s, off);
    __syncthreads();
    if (lane == 0) wf[warp] = s;
    __syncthreads();
    if (warp == 0) {
        float t = (lane < 8) ? wf[lane] : 0.f;
        #pragma unroll
        for (int off = 4; off; off >>= 1) t += __shfl_xor_sync(FULLMASK, t, off);
        if (lane == 0) g_rowsum[r] = t;
    }

    // ---- 4 rounds of masked argmax -> candidate list ----
    for (int round = 0; round < TCAND; round++) {
        u32 bk = 0, bc = 0xFFFFFFFFu;
        #pragma unroll
        for (int k = 0; k < 4; k++) {
            #pragma unroll
            for (int j = 0; j < 4; j++) {
                int e = k * 4 + j;
                if (freeMask & (1u << e)) {
                    u32 kk = orderKey(vals[e]);
                    if (kk > bk) { bk = kk; bc = (u32)(fidx[k] * 4 + j); }
                }
            }
        }
        #pragma unroll
        for (int off = 16; off; off >>= 1) {
            u32 ok = __shfl_xor_sync(FULLMASK, bk, off);
            u32 oc = __shfl_xor_sync(FULLMASK, bc, off);
            if (ok > bk || (ok == bk && oc < bc)) { bk = ok; bc = oc; }
        }
        if (lane == 0) { wk[warp] = bk; wc[warp] = bc; }
        __syncthreads();
        if (warp == 0) {
            u32 tk = (lane < 8) ? wk[lane] : 0u;
            u32 tc = (lane < 8) ? wc[lane] : 0xFFFFFFFFu;
            #pragma unroll
            for (int off = 4; off; off >>= 1) {
                u32 ok = __shfl_xor_sync(FULLMASK, tk, off);
                u32 oc = __shfl_xor_sync(FULLMASK, tc, off);
                if (ok > tk || (ok == tk && oc < tc)) { tk = ok; tc = oc; }
            }
            if (lane == 0) {
                g_cand[r * TCAND + round] = tk ? (((u64)tk << 32) | tc) : 0ull;
                s_wincol = tk ? tc : 0xFFFFFFFFu;
            }
        }
        __syncthreads();
        u32 cw = s_wincol;
        if (cw != 0xFFFFFFFFu) {
            int f = (int)(cw >> 2);
            if ((f & 255) == tid) {
                int k = f >> 8, j = (int)(cw & 3u);
                freeMask &= ~(1u << (k * 4 + j));
            }
        }
        __syncthreads();
    }
}

// ---------------- K2: global max + global sum (from row stats) -----------
__global__ void __launch_bounds__(1024) k2_global() {
    int tid = threadIdx.x, lane = tid & 31, warp = tid >> 5;
    __shared__ float w[32];
    __shared__ float s_gm;
    float rm = g_rowmax[tid];
    float m = rm;
    #pragma unroll
    for (int off = 16; off; off >>= 1) m = fmaxf(m, __shfl_xor_sync(FULLMASK, m, off));
    if (lane == 0) w[warp] = m;
    __syncthreads();
    if (warp == 0) {
        float t = w[lane];
        #pragma unroll
        for (int off = 16; off; off >>= 1) t = fmaxf(t, __shfl_xor_sync(FULLMASK, t, off));
        if (lane == 0) s_gm = t;
    }
    __syncthreads();
    float gm = s_gm;
    float s = g_rowsum[tid] * __expf(rm - gm);
    #pragma unroll
    for (int off = 16; off; off >>= 1) s += __shfl_xor_sync(FULLMASK, s, off);
    __syncthreads();
    if (lane == 0) w[warp] = s;
    __syncthreads();
    if (warp == 0) {
        float t = w[lane];
        #pragma unroll
        for (int off = 16; off; off >>= 1) t += __shfl_xor_sync(FULLMASK, t, off);
        if (lane == 0) { g_gmax = gm; g_gsum = t; }
    }
}

// ---------------- K4: write normalized policy ----------------------------
__global__ void __launch_bounds__(256) k4_policy(const float* __restrict__ scores,
                                                 float* __restrict__ out_pol) {
    const float gm = g_gmax;
    const float inv = 1.0f / g_gsum;
    int i = blockIdx.x * 256 + threadIdx.x;
    const float4* p = (const float4*)scores;
    float4* o = (float4*)out_pol;
    float4 a = p[i];
    float4 b = p[i + 524288];
    float4 ra, rb;
    ra.x = __expf(a.x - gm) * inv; ra.y = __expf(a.y - gm) * inv;
    ra.z = __expf(a.z - gm) * inv; ra.w = __expf(a.w - gm) * inv;
    rb.x = __expf(b.x - gm) * inv; rb.y = __expf(b.y - gm) * inv;
    rb.z = __expf(b.z - gm) * inv; rb.w = __expf(b.w - gm) * inv;
    o[i] = ra;
    o[i + 524288] = rb;
}

// ---------------- K5: greedy assignment — register offers + rounds -------
__device__ __forceinline__ void ins4(u64& A, u64& B, u64& C, u64& D, u64 h) {
    if (h > C) {
        if (h > A)      { D = C; C = B; B = A; A = h; }
        else if (h > B) { D = C; C = B; B = h; }
        else            { D = C; C = h; }
    } else if (h > D)   { D = h; }
}

__global__ void __launch_bounds__(1024, 1) k5_assign(
        const float* __restrict__ scores,
        const int* __restrict__ cont,
        const int* __restrict__ prev,
        float* __restrict__ out_act) {
    __shared__ __align__(16) u64 sheads[MM];          // 8KB packed heads
    __shared__ __align__(16) u64 scand[MM * TCAND];   // 32KB candidate lists
    __shared__ u32 colbits[NN / 32];                  // 512B col bitmask
    __shared__ unsigned char hptr[MM];                // 1KB next cand index
    __shared__ int Ksh;
    __shared__ int rs_n;
    __shared__ unsigned short rs_rows[MM];            // 2KB rescan queue

    const int tid = threadIdx.x;

    // -------- prologue: full block builds shared state --------
    #pragma unroll
    for (int k = 0; k < TCAND; k++) {
        int idx = tid + k * 1024;
        scand[idx] = g_cand[idx];
    }
    if (tid < NN / 32) colbits[tid] = g_colbits[tid];
    {
        u64 c0 = g_cand[tid * TCAND];
        u32 key = (u32)(c0 >> 32);
        u32 col = (u32)c0 & 0xFFFu;
        sheads[tid] = key ? packHead(key, ((u32)tid << 12) | col) : 0ull;
    }
    hptr[tid] = 1;
    int myCont = cont[tid];
    out_act[tid] = myCont ? (float)prev[tid] : -1.0f;
    int K = __syncthreads_count(myCont == 0);
    if (tid == 0) { Ksh = K; rs_n = 0; }
    __syncthreads();
    if (tid >= 32) return;     // only warp 0 continues

    const int lane = tid;
    const int base = lane * 32;
    const int K2 = Ksh;

    int assigned = 0;
    bool done = false;
    int guard = 0;

    while (!done && assigned < K2) {
        if (++guard > 16384) break;                  // safety (never hit)

        // ================= REFILL (all lanes in parallel) =================
        if (lane == 0) rs_n = 0;
        __syncwarp(FULLMASK);

        u64 A = 0, B = 0, C = 0, D = 0;
        const ulonglong2* sp = (const ulonglong2*)(sheads + base);
        #pragma unroll 4
        for (int q = 0; q < 16; q++) {
            ulonglong2 hh = sp[q];
            #pragma unroll
            for (int half = 0; half < 2; half++) {
                u64 h = half ? hh.y : hh.x;
                if (!h) continue;
                int r = base + q * 2 + half;
                u32 rc = 0x400000u - (u32)(h & 0x7FFFFFu);
                u32 c  = rc & 0xFFFu;
                if ((colbits[c >> 5] >> (c & 31)) & 1u) {
                    // stale head: pop candidate list (parallel across lanes)
                    int p = hptr[r];
                    u64 nh = 0ull;
                    while (p < TCAND) {
                        u64 cd = scand[(r << 2) + p];
                        p++;
                        u32 kk = (u32)(cd >> 32);
                        if (!kk) { p = TCAND; break; }
                        u32 cc = (u32)cd & 0xFFFu;
                        if (!((colbits[cc >> 5] >> (cc & 31)) & 1u)) {
                            nh = packHead(kk, ((u32)r << 12) | cc);
                            break;
                        }
                    }
                    hptr[r] = (unsigned char)p;
                    sheads[r] = nh;
                    if (!nh) { int ix = atomicAdd(&rs_n, 1); rs_rows[ix] = (unsigned short)r; }
                    h = nh;
                }
                if (h) ins4(A, B, C, D, h);
            }
        }
        __syncwarp(FULLMASK);
        int nrs = rs_n;
        if (nrs > 0) {
            // warp-cooperative exact rescans (rare)
            for (int i = 0; i < nrs; i++) {
                int r = rs_rows[i];
                const float4* rp = (const float4*)(scores + (size_t)r * NN);
                u32 bk = 0, bc = 0xFFFu;
                #pragma unroll 4
                for (int q = 0; q < 32; q++) {
                    int f = lane + q * 32;
                    float4 vv = rp[f];
                    int c0i = f * 4;
                    float arr[4] = { vv.x, vv.y, vv.z, vv.w };
                    #pragma unroll
                    for (int j = 0; j < 4; j++) {
                        int cc = c0i + j;
                        if (!((colbits[cc >> 5] >> (cc & 31)) & 1u)) {
                            u32 kk = orderKey(arr[j]);
                            if (kk > bk) { bk = kk; bc = (u32)cc; }
                        }
                    }
                }
                u32 mk = __reduce_max_sync(FULLMASK, bk);
                u32 pc = (bk == mk) ? (0x1000u - bc) : 0u;
                u32 ps = __reduce_max_sync(FULLMASK, pc);
                if (lane == (r >> 5)) {
                    sheads[r] = mk ? packHead(mk, ((u32)r << 12) | (0x1000u - ps)) : 0ull;
                    hptr[r] = TCAND;
                }
            }
            __syncwarp(FULLMASK);
            // heads changed: rebuild register offers (all fresh now)
            A = B = C = D = 0;
            #pragma unroll 4
            for (int q = 0; q < 16; q++) {
                ulonglong2 hh = sp[q];
                if (hh.x) ins4(A, B, C, D, hh.x);
                if (hh.y) ins4(A, B, C, D, hh.y);
            }
        }
        int rem = (A != 0) + (B != 0) + (C != 0) + (D != 0);

        // ================= COMMIT loop (no smem rescans) =================
        for (;;) {
            u32 k1 = (u32)(A >> 23);
            u32 mx = __reduce_max_sync(FULLMASK, k1);
            if (mx == 0) { done = true; break; }     // nothing left anywhere
            u32 cnd = (k1 == mx) ? (u32)(A & 0x7FFFFFu) : 0u;
            u32 sel = __reduce_max_sync(FULLMASK, cnd);
            u32 rc = 0x400000u - sel;
            int a = (int)(rc >> 12);
            int t = (int)(rc & 0xFFFu);
            int wl = a >> 5;                         // winner lane owns row a
            int ev = 0;                              // 0=commit, 1=commit+end, 2=stale+end
            if (lane == wl) {
                u32 w = colbits[t >> 5], bit = 1u << (t & 31);
                if (w & bit) {
                    ev = 2;                          // stale: refill will pop it
                } else {
                    colbits[t >> 5] = w | bit;
                    out_act[a] = (float)t;
                    sheads[a] = 0ull;
                    A = B; B = C; C = D; D = 0;
                    ev = (--rem == 0) ? 1 : 0;       // last offer -> end round
                }
            }
            ev = __shfl_sync(FULLMASK, ev, wl);
            __syncwarp(FULLMASK);                    // colbits/sheads visible
            if (ev != 2) {
                assigned++;
                if (assigned >= K2) { done = true; break; }
            }
            if (ev) break;                           // end of round
        }
    }
}

// ---------------- launch ---------------------------------------------------
extern "C" void kernel_launch(void* const* d_in, const int* in_sizes, int n_in,
                              void* d_out, int out_size) {
    const float* scores = (const float*)d_in[0];
    const int*   cont   = (const int*)d_in[1];
    const int*   prev   = (const int*)d_in[2];
    float* out = (float*)d_out;      // [0..1023] actions, [1024..] policy

    k0_colhit<<<1, 1024>>>(cont, prev);
    k1_row<<<MM, 256>>>(scores, cont);
    k2_global<<<1, 1024>>>();
    k4_policy<<<2048, 256>>>(scores, out + MM);
    k5_assign<<<1, 1024>>>(scores, cont, prev, out);
}

// round 5
// speedup vs baseline: 1.9533x; 1.9533x over previous
#include <cuda_runtime.h>
#include <cstdint>

#define MM 1024
#define NN 4096
#define TCAND 4
#define FULLMASK 0xffffffffu

typedef unsigned int       u32;
typedef unsigned long long u64;

// ---------------- device scratch (no allocations allowed) ----------------
__device__ int   g_colhit[NN];
__device__ u32   g_colbits[NN / 32];
__device__ float g_rowmax[MM];
__device__ float g_rowsum[MM];
__device__ u64   g_cand[MM * TCAND];   // per-row top-4: key<<32 | col
__device__ float g_gmax;
__device__ float g_gsum;

// Monotonic float -> uint32 ordering key (nonzero for all real floats).
__device__ __forceinline__ u32 orderKey(float v) {
    u32 b = __float_as_uint(v);
    return (b & 0x80000000u) ? ~b : (b | 0x80000000u);
}

// Packed head: key high, inverted flat index (row<<12|col) low 23 bits.
// u64 max == (max key, then smallest flat index) — exact reference tie-break.
__device__ __forceinline__ u64 packHead(u32 key, u32 rc) {
    return ((u64)key << 23) | (u64)(0x400000u - rc);
}

// ---------------- K0: column-hit mask (bytes + bitmask) ------------------
__global__ void k0_colhit(const int* __restrict__ cont, const int* __restrict__ prev) {
    int tid = threadIdx.x;                 // 1024 threads
    #pragma unroll
    for (int k = 0; k < 4; k++) g_colhit[tid + k * 1024] = 0;
    if (tid < NN / 32) g_colbits[tid] = 0;
    __syncthreads();
    if (cont[tid]) {
        int c = prev[tid];
        g_colhit[c] = 1;                                  // benign races
        atomicOr(&g_colbits[c >> 5], 1u << (c & 31));
    }
}

// ---------------- K1: per-row rowmax, sumexp, top-4 masked candidates ----
__global__ void __launch_bounds__(256) k1_row(const float* __restrict__ scores,
                                              const int* __restrict__ cont) {
    const int r = blockIdx.x, tid = threadIdx.x, lane = tid & 31, warp = tid >> 5;
    __shared__ float wf[8];
    __shared__ u32   wk[8], wc[8];
    __shared__ float s_bcast;
    __shared__ u32   s_wincol;

    const float4* row = (const float4*)(scores + (size_t)r * NN);
    const bool isCont = (cont[r] != 0);

    float vals[16];
    int   fidx[4];
    #pragma unroll
    for (int k = 0; k < 4; k++) {
        int f = tid + k * 256; fidx[k] = f;
        float4 v = row[f];
        vals[k * 4 + 0] = v.x; vals[k * 4 + 1] = v.y;
        vals[k * 4 + 2] = v.z; vals[k * 4 + 3] = v.w;
    }
    u32 freeMask = 0;
    if (!isCont) {
        #pragma unroll
        for (int k = 0; k < 4; k++) {
            int4 h = ((const int4*)g_colhit)[fidx[k]];
            if (!h.x) freeMask |= 1u << (k * 4 + 0);
            if (!h.y) freeMask |= 1u << (k * 4 + 1);
            if (!h.z) freeMask |= 1u << (k * 4 + 2);
            if (!h.w) freeMask |= 1u << (k * 4 + 3);
        }
    }

    // ---- raw row max ----
    float m = vals[0];
    #pragma unroll
    for (int e = 1; e < 16; e++) m = fmaxf(m, vals[e]);
    #pragma unroll
    for (int off = 16; off; off >>= 1) m = fmaxf(m, __shfl_xor_sync(FULLMASK, m, off));
    if (lane == 0) wf[warp] = m;
    __syncthreads();
    if (warp == 0) {
        float t = (lane < 8) ? wf[lane] : -3.4e38f;
        #pragma unroll
        for (int off = 4; off; off >>= 1) t = fmaxf(t, __shfl_xor_sync(FULLMASK, t, off));
        if (lane == 0) { s_bcast = t; g_rowmax[r] = t; }
    }
    __syncthreads();
    float rowmax = s_bcast;

    // ---- row sumexp (stable at rowmax) ----
    float s = 0.f;
    #pragma unroll
    for (int e = 0; e < 16; e++) s += __expf(vals[e] - rowmax);
    #pragma unroll
    for (int off = 16; off; off >>= 1) s += __shfl_xor_sync(FULLMASK, s, off);
    __syncthreads();
    if (lane == 0) wf[warp] = s;
    __syncthreads();
    if (warp == 0) {
        float t = (lane < 8) ? wf[lane] : 0.f;
        #pragma unroll
        for (int off = 4; off; off >>= 1) t += __shfl_xor_sync(FULLMASK, t, off);
        if (lane == 0) g_rowsum[r] = t;
    }

    // ---- 4 rounds of masked argmax -> candidate list ----
    for (int round = 0; round < TCAND; round++) {
        u32 bk = 0, bc = 0xFFFFFFFFu;
        #pragma unroll
        for (int k = 0; k < 4; k++) {
            #pragma unroll
            for (int j = 0; j < 4; j++) {
                int e = k * 4 + j;
                if (freeMask & (1u << e)) {
                    u32 kk = orderKey(vals[e]);
                    if (kk > bk) { bk = kk; bc = (u32)(fidx[k] * 4 + j); }
                }
            }
        }
        #pragma unroll
        for (int off = 16; off; off >>= 1) {
            u32 ok = __shfl_xor_sync(FULLMASK, bk, off);
            u32 oc = __shfl_xor_sync(FULLMASK, bc, off);
            if (ok > bk || (ok == bk && oc < bc)) { bk = ok; bc = oc; }
        }
        if (lane == 0) { wk[warp] = bk; wc[warp] = bc; }
        __syncthreads();
        if (warp == 0) {
            u32 tk = (lane < 8) ? wk[lane] : 0u;
            u32 tc = (lane < 8) ? wc[lane] : 0xFFFFFFFFu;
            #pragma unroll
            for (int off = 4; off; off >>= 1) {
                u32 ok = __shfl_xor_sync(FULLMASK, tk, off);
                u32 oc = __shfl_xor_sync(FULLMASK, tc, off);
                if (ok > tk || (ok == tk && oc < tc)) { tk = ok; tc = oc; }
            }
            if (lane == 0) {
                g_cand[r * TCAND + round] = tk ? (((u64)tk << 32) | tc) : 0ull;
                s_wincol = tk ? tc : 0xFFFFFFFFu;
            }
        }
        __syncthreads();
        u32 cw = s_wincol;
        if (cw != 0xFFFFFFFFu) {
            int f = (int)(cw >> 2);
            if ((f & 255) == tid) {
                int k = f >> 8, j = (int)(cw & 3u);
                freeMask &= ~(1u << (k * 4 + j));
            }
        }
        __syncthreads();
    }
}

// ---------------- K2: global max + global sum (from row stats) -----------
__global__ void __launch_bounds__(1024) k2_global() {
    int tid = threadIdx.x, lane = tid & 31, warp = tid >> 5;
    __shared__ float w[32];
    __shared__ float s_gm;
    float rm = g_rowmax[tid];
    float m = rm;
    #pragma unroll
    for (int off = 16; off; off >>= 1) m = fmaxf(m, __shfl_xor_sync(FULLMASK, m, off));
    if (lane == 0) w[warp] = m;
    __syncthreads();
    if (warp == 0) {
        float t = w[lane];
        #pragma unroll
        for (int off = 16; off; off >>= 1) t = fmaxf(t, __shfl_xor_sync(FULLMASK, t, off));
        if (lane == 0) s_gm = t;
    }
    __syncthreads();
    float gm = s_gm;
    float s = g_rowsum[tid] * __expf(rm - gm);
    #pragma unroll
    for (int off = 16; off; off >>= 1) s += __shfl_xor_sync(FULLMASK, s, off);
    __syncthreads();
    if (lane == 0) w[warp] = s;
    __syncthreads();
    if (warp == 0) {
        float t = w[lane];
        #pragma unroll
        for (int off = 16; off; off >>= 1) t += __shfl_xor_sync(FULLMASK, t, off);
        if (lane == 0) { g_gmax = gm; g_gsum = t; }
    }
}

// ---------------- K4: write normalized policy ----------------------------
__global__ void __launch_bounds__(256) k4_policy(const float* __restrict__ scores,
                                                 float* __restrict__ out_pol) {
    const float gm = g_gmax;
    const float inv = 1.0f / g_gsum;
    int i = blockIdx.x * 256 + threadIdx.x;
    const float4* p = (const float4*)scores;
    float4* o = (float4*)out_pol;
    float4 a = p[i];
    float4 b = p[i + 524288];
    float4 ra, rb;
    ra.x = __expf(a.x - gm) * inv; ra.y = __expf(a.y - gm) * inv;
    ra.z = __expf(a.z - gm) * inv; ra.w = __expf(a.w - gm) * inv;
    rb.x = __expf(b.x - gm) * inv; rb.y = __expf(b.y - gm) * inv;
    rb.z = __expf(b.z - gm) * inv; rb.w = __expf(b.w - gm) * inv;
    o[i] = ra;
    o[i + 524288] = rb;
}

// ---------------- K5: greedy assignment — hierarchical group maxes -------
// Lane i owns rows [32i, 32i+32) as 8 groups of 4 rows each. Group maxes
// live in registers G0..G7; p1 = max(G*). On commit/pop only the affected
// group (2 LDS.128) is reloaded — no full 32-head rescan.
__device__ __forceinline__ u64 u64max(u64 a, u64 b) { return a > b ? a : b; }

__device__ __forceinline__ u64 grpmax(const ulonglong2* sp, int g) {
    ulonglong2 x = sp[g * 2];
    ulonglong2 y = sp[g * 2 + 1];
    return u64max(u64max(x.x, x.y), u64max(y.x, y.y));
}

#define TREEMAX8(G0,G1,G2,G3,G4,G5,G6,G7) \
    u64max(u64max(u64max(G0,G1), u64max(G2,G3)), \
           u64max(u64max(G4,G5), u64max(G6,G7)))

#define SETGRP(g, v) do { switch (g) { \
    case 0: G0 = (v); break; case 1: G1 = (v); break; \
    case 2: G2 = (v); break; case 3: G3 = (v); break; \
    case 4: G4 = (v); break; case 5: G5 = (v); break; \
    case 6: G6 = (v); break; default: G7 = (v); break; } } while (0)

__global__ void __launch_bounds__(1024, 1) k5_assign(
        const float* __restrict__ scores,
        const int* __restrict__ cont,
        const int* __restrict__ prev,
        float* __restrict__ out_act) {
    __shared__ __align__(16) u64 sheads[MM];          // 8KB packed heads
    __shared__ __align__(16) u64 scand[MM * TCAND];   // 32KB candidate lists
    __shared__ u32 colbits[NN / 32];                  // 512B col bitmask
    __shared__ unsigned char hptr[MM];                // 1KB next cand index
    __shared__ int Ksh;

    const int tid = threadIdx.x;

    // -------- prologue: full block builds shared state --------
    #pragma unroll
    for (int k = 0; k < TCAND; k++) {
        int idx = tid + k * 1024;
        scand[idx] = g_cand[idx];
    }
    if (tid < NN / 32) colbits[tid] = g_colbits[tid];
    {
        u64 c0 = g_cand[tid * TCAND];
        u32 key = (u32)(c0 >> 32);
        u32 col = (u32)c0 & 0xFFFu;
        sheads[tid] = key ? packHead(key, ((u32)tid << 12) | col) : 0ull;
    }
    hptr[tid] = 1;
    int myCont = cont[tid];
    out_act[tid] = myCont ? (float)prev[tid] : -1.0f;
    int K = __syncthreads_count(myCont == 0);
    if (tid == 0) Ksh = K;
    __syncthreads();
    if (tid >= 32) return;     // only warp 0 continues

    const int lane = tid;
    const int base = lane * 32;
    const int K2 = Ksh;
    const ulonglong2* sp = (const ulonglong2*)(sheads + base);

    u64 G0 = grpmax(sp, 0), G1 = grpmax(sp, 1), G2 = grpmax(sp, 2), G3 = grpmax(sp, 3);
    u64 G4 = grpmax(sp, 4), G5 = grpmax(sp, 5), G6 = grpmax(sp, 6), G7 = grpmax(sp, 7);
    u64 p1 = TREEMAX8(G0, G1, G2, G3, G4, G5, G6, G7);

    int assigned = 0;
    int guard = 0;

    while (assigned < K2) {
        if (++guard > 16384) break;                 // safety (never hit)
        u32 k1 = (u32)(p1 >> 23);
        u32 mx = __reduce_max_sync(FULLMASK, k1);
        if (mx == 0) break;
        u32 cnd = (k1 == mx) ? (u32)(p1 & 0x7FFFFFu) : 0u;  // nonzero iff live
        u32 sel = __reduce_max_sync(FULLMASK, cnd);
        u32 rc = 0x400000u - sel;                   // all lanes know (row,col)
        int a = (int)(rc >> 12);
        int t = (int)(rc & 0xFFFu);
        bool owner = (lane == (a >> 5));            // unique: rows partitioned
        u32 cw = colbits[t >> 5];                   // broadcast LDS
        bool taken = (cw >> (t & 31)) & 1u;

        if (!taken) {
            if (owner) {
                colbits[t >> 5] = cw | (1u << (t & 31));
                out_act[a] = (float)t;
                sheads[a] = 0ull;
                int g = (a >> 2) & 7;
                u64 ng = grpmax(sp, g);
                SETGRP(g, ng);
                p1 = TREEMAX8(G0, G1, G2, G3, G4, G5, G6, G7);
            }
            assigned++;
        } else {
            // stale head of row a: owner pops its candidate list
            int need = 0;
            if (owner) {
                int p = hptr[a];
                u64 np = 0ull;
                if (p >= TCAND) {
                    need = 1;
                } else {
                    while (p < TCAND) {
                        u64 cd = scand[(a << 2) + p];
                        p++;
                        u32 kk = (u32)(cd >> 32);
                        if (!kk) { p = TCAND; break; }
                        u32 cc = (u32)cd & 0xFFFu;
                        if (!((colbits[cc >> 5] >> (cc & 31)) & 1u)) {
                            np = packHead(kk, ((u32)a << 12) | cc);
                            break;
                        }
                    }
                    hptr[a] = (unsigned char)p;
                    if (np) {
                        sheads[a] = np;
                        int g = (a >> 2) & 7;
                        u64 ng = grpmax(sp, g);
                        SETGRP(g, ng);
                        p1 = TREEMAX8(G0, G1, G2, G3, G4, G5, G6, G7);
                    } else need = 1;
                }
            }
            unsigned nb = __ballot_sync(FULLMASK, owner && need);
            if (nb) {
                // rare: warp-cooperative exact rescan of row a from L2/global
                const float4* rp = (const float4*)(scores + (size_t)a * NN);
                u32 bk = 0, bc = 0xFFFu;
                #pragma unroll 4
                for (int q = 0; q < 32; q++) {
                    int f = lane + q * 32;
                    float4 vv = rp[f];
                    int c0i = f * 4;
                    float arr[4] = { vv.x, vv.y, vv.z, vv.w };
                    #pragma unroll
                    for (int j = 0; j < 4; j++) {
                        int cc = c0i + j;
                        if (!((colbits[cc >> 5] >> (cc & 31)) & 1u)) {
                            u32 kk = orderKey(arr[j]);
                            if (kk > bk) { bk = kk; bc = (u32)cc; }
                        }
                    }
                }
                u32 mk = __reduce_max_sync(FULLMASK, bk);
                u32 pc = (bk == mk) ? (0x1000u - bc) : 0u;
                u32 ps = __reduce_max_sync(FULLMASK, pc);
                if (owner) {
                    sheads[a] = mk ? packHead(mk, ((u32)a << 12) | (0x1000u - ps)) : 0ull;
                    hptr[a] = TCAND;      // future pops rescan again
                    int g = (a >> 2) & 7;
                    u64 ng = grpmax(sp, g);
                    SETGRP(g, ng);
                    p1 = TREEMAX8(G0, G1, G2, G3, G4, G5, G6, G7);
                }
            }
        }
        __syncwarp(FULLMASK);   // make colbits/sheads writes visible
    }
}

// ---------------- launch ---------------------------------------------------
extern "C" void kernel_launch(void* const* d_in, const int* in_sizes, int n_in,
                              void* d_out, int out_size) {
    const float* scores = (const float*)d_in[0];
    const int*   cont   = (const int*)d_in[1];
    const int*   prev   = (const int*)d_in[2];
    float* out = (float*)d_out;      // [0..1023] actions, [1024..] policy

    k0_colhit<<<1, 1024>>>(cont, prev);
    k1_row<<<MM, 256>>>(scores, cont);
    k2_global<<<1, 1024>>>();
    k4_policy<<<2048, 256>>>(scores, out + MM);
    k5_assign<<<1, 1024>>>(scores, cont, prev, out);
}

// round 6
// speedup vs baseline: 2.1416x; 1.0964x over previous
#include <cuda_runtime.h>
#include <cstdint>

#define MM 1024
#define NN 4096
#define TCAND 4
#define FULLMASK 0xffffffffu

typedef unsigned int       u32;
typedef unsigned long long u64;

// ---------------- device scratch (no allocations allowed) ----------------
__device__ int   g_colhit[NN];
__device__ u32   g_colbits[NN / 32];
__device__ float g_rowmax[MM];
__device__ float g_rowsum[MM];
__device__ u64   g_cand[MM * TCAND];   // per-row top-4: key<<32 | col
__device__ float g_gmax;
__device__ float g_gsum;

// Monotonic float -> uint32 ordering key (nonzero for all real floats).
__device__ __forceinline__ u32 orderKey(float v) {
    u32 b = __float_as_uint(v);
    return (b & 0x80000000u) ? ~b : (b | 0x80000000u);
}

// Packed head: key high, inverted flat index (row<<12|col) low 23 bits.
// u64 max == (max key, then smallest flat index) — exact reference tie-break.
__device__ __forceinline__ u64 packHead(u32 key, u32 rc) {
    return ((u64)key << 23) | (u64)(0x400000u - rc);
}

// ---------------- K0: column-hit mask (bytes + bitmask) ------------------
__global__ void k0_colhit(const int* __restrict__ cont, const int* __restrict__ prev) {
    int tid = threadIdx.x;                 // 1024 threads
    #pragma unroll
    for (int k = 0; k < 4; k++) g_colhit[tid + k * 1024] = 0;
    if (tid < NN / 32) g_colbits[tid] = 0;
    __syncthreads();
    if (cont[tid]) {
        int c = prev[tid];
        g_colhit[c] = 1;                                  // benign races
        atomicOr(&g_colbits[c >> 5], 1u << (c & 31));
    }
}

// ---------------- K1: per-row rowmax, sumexp, top-4 masked candidates ----
__global__ void __launch_bounds__(256) k1_row(const float* __restrict__ scores,
                                              const int* __restrict__ cont) {
    const int r = blockIdx.x, tid = threadIdx.x, lane = tid & 31, warp = tid >> 5;
    __shared__ float wf[8];
    __shared__ u32   wk[8], wc[8];
    __shared__ float s_bcast;
    __shared__ u32   s_wincol;

    const float4* row = (const float4*)(scores + (size_t)r * NN);
    const bool isCont = (cont[r] != 0);

    float vals[16];
    int   fidx[4];
    #pragma unroll
    for (int k = 0; k < 4; k++) {
        int f = tid + k * 256; fidx[k] = f;
        float4 v = row[f];
        vals[k * 4 + 0] = v.x; vals[k * 4 + 1] = v.y;
        vals[k * 4 + 2] = v.z; vals[k * 4 + 3] = v.w;
    }
    u32 freeMask = 0;
    if (!isCont) {
        #pragma unroll
        for (int k = 0; k < 4; k++) {
            int4 h = ((const int4*)g_colhit)[fidx[k]];
            if (!h.x) freeMask |= 1u << (k * 4 + 0);
            if (!h.y) freeMask |= 1u << (k * 4 + 1);
            if (!h.z) freeMask |= 1u << (k * 4 + 2);
            if (!h.w) freeMask |= 1u << (k * 4 + 3);
        }
    }

    // ---- raw row max ----
    float m = vals[0];
    #pragma unroll
    for (int e = 1; e < 16; e++) m = fmaxf(m, vals[e]);
    #pragma unroll
    for (int off = 16; off; off >>= 1) m = fmaxf(m, __shfl_xor_sync(FULLMASK, m, off));
    if (lane == 0) wf[warp] = m;
    __syncthreads();
    if (warp == 0) {
        float t = (lane < 8) ? wf[lane] : -3.4e38f;
        #pragma unroll
        for (int off = 4; off; off >>= 1) t = fmaxf(t, __shfl_xor_sync(FULLMASK, t, off));
        if (lane == 0) { s_bcast = t; g_rowmax[r] = t; }
    }
    __syncthreads();
    float rowmax = s_bcast;

    // ---- row sumexp (stable at rowmax) ----
    float s = 0.f;
    #pragma unroll
    for (int e = 0; e < 16; e++) s += __expf(vals[e] - rowmax);
    #pragma unroll
    for (int off = 16; off; off >>= 1) s += __shfl_xor_sync(FULLMASK, s, off);
    __syncthreads();
    if (lane == 0) wf[warp] = s;
    __syncthreads();
    if (warp == 0) {
        float t = (lane < 8) ? wf[lane] : 0.f;
        #pragma unroll
        for (int off = 4; off; off >>= 1) t += __shfl_xor_sync(FULLMASK, t, off);
        if (lane == 0) g_rowsum[r] = t;
    }

    // ---- 4 rounds of masked argmax -> candidate list ----
    for (int round = 0; round < TCAND; round++) {
        u32 bk = 0, bc = 0xFFFFFFFFu;
        #pragma unroll
        for (int k = 0; k < 4; k++) {
            #pragma unroll
            for (int j = 0; j < 4; j++) {
                int e = k * 4 + j;
                if (freeMask & (1u << e)) {
                    u32 kk = orderKey(vals[e]);
                    if (kk > bk) { bk = kk; bc = (u32)(fidx[k] * 4 + j); }
                }
            }
        }
        #pragma unroll
        for (int off = 16; off; off >>= 1) {
            u32 ok = __shfl_xor_sync(FULLMASK, bk, off);
            u32 oc = __shfl_xor_sync(FULLMASK, bc, off);
            if (ok > bk || (ok == bk && oc < bc)) { bk = ok; bc = oc; }
        }
        if (lane == 0) { wk[warp] = bk; wc[warp] = bc; }
        __syncthreads();
        if (warp == 0) {
            u32 tk = (lane < 8) ? wk[lane] : 0u;
            u32 tc = (lane < 8) ? wc[lane] : 0xFFFFFFFFu;
            #pragma unroll
            for (int off = 4; off; off >>= 1) {
                u32 ok = __shfl_xor_sync(FULLMASK, tk, off);
                u32 oc = __shfl_xor_sync(FULLMASK, tc, off);
                if (ok > tk || (ok == tk && oc < tc)) { tk = ok; tc = oc; }
            }
            if (lane == 0) {
                g_cand[r * TCAND + round] = tk ? (((u64)tk << 32) | tc) : 0ull;
                s_wincol = tk ? tc : 0xFFFFFFFFu;
            }
        }
        __syncthreads();
        u32 cw = s_wincol;
        if (cw != 0xFFFFFFFFu) {
            int f = (int)(cw >> 2);
            if ((f & 255) == tid) {
                int k = f >> 8, j = (int)(cw & 3u);
                freeMask &= ~(1u << (k * 4 + j));
            }
        }
        __syncthreads();
    }
}

// ---------------- K2: global max + global sum (from row stats) -----------
__global__ void __launch_bounds__(1024) k2_global() {
    int tid = threadIdx.x, lane = tid & 31, warp = tid >> 5;
    __shared__ float w[32];
    __shared__ float s_gm;
    float rm = g_rowmax[tid];
    float m = rm;
    #pragma unroll
    for (int off = 16; off; off >>= 1) m = fmaxf(m, __shfl_xor_sync(FULLMASK, m, off));
    if (lane == 0) w[warp] = m;
    __syncthreads();
    if (warp == 0) {
        float t = w[lane];
        #pragma unroll
        for (int off = 16; off; off >>= 1) t = fmaxf(t, __shfl_xor_sync(FULLMASK, t, off));
        if (lane == 0) s_gm = t;
    }
    __syncthreads();
    float gm = s_gm;
    float s = g_rowsum[tid] * __expf(rm - gm);
    #pragma unroll
    for (int off = 16; off; off >>= 1) s += __shfl_xor_sync(FULLMASK, s, off);
    __syncthreads();
    if (lane == 0) w[warp] = s;
    __syncthreads();
    if (warp == 0) {
        float t = w[lane];
        #pragma unroll
        for (int off = 16; off; off >>= 1) t += __shfl_xor_sync(FULLMASK, t, off);
        if (lane == 0) { g_gmax = gm; g_gsum = t; }
    }
}

// ---------------- K4: write normalized policy ----------------------------
__global__ void __launch_bounds__(256) k4_policy(const float* __restrict__ scores,
                                                 float* __restrict__ out_pol) {
    const float gm = g_gmax;
    const float inv = 1.0f / g_gsum;
    int i = blockIdx.x * 256 + threadIdx.x;
    const float4* p = (const float4*)scores;
    float4* o = (float4*)out_pol;
    float4 a = p[i];
    float4 b = p[i + 524288];
    float4 ra, rb;
    ra.x = __expf(a.x - gm) * inv; ra.y = __expf(a.y - gm) * inv;
    ra.z = __expf(a.z - gm) * inv; ra.w = __expf(a.w - gm) * inv;
    rb.x = __expf(b.x - gm) * inv; rb.y = __expf(b.y - gm) * inv;
    rb.z = __expf(b.z - gm) * inv; rb.w = __expf(b.w - gm) * inv;
    o[i] = ra;
    o[i + 524288] = rb;
}

// ---------------- K5: greedy assignment — replicated, branch-free commit -
// Invariant: in the common (commit) path, EVERY lane performs every smem
// store (same address, same value). Each lane's smem view is therefore
// self-consistent by program order alone -> no __syncwarp, no divergence.
__device__ __forceinline__ u64 u64max(u64 a, u64 b) { return a > b ? a : b; }

#define TREEMAX8(G0,G1,G2,G3,G4,G5,G6,G7) \
    u64max(u64max(u64max(G0,G1), u64max(G2,G3)), \
           u64max(u64max(G4,G5), u64max(G6,G7)))

__global__ void __launch_bounds__(1024, 1) k5_assign(
        const float* __restrict__ scores,
        const int* __restrict__ cont,
        const int* __restrict__ prev,
        float* __restrict__ out_act) {
    __shared__ __align__(16) u64 sheads[MM];          // 8KB packed heads
    __shared__ __align__(16) u64 scand[MM * TCAND];   // 32KB candidate lists
    __shared__ u32 colbits[NN / 32];                  // 512B col bitmask
    __shared__ unsigned char hptr[MM];                // 1KB next cand index
    __shared__ int Ksh;

    const int tid = threadIdx.x;

    // -------- prologue: full block builds shared state --------
    #pragma unroll
    for (int k = 0; k < TCAND; k++) {
        int idx = tid + k * 1024;
        scand[idx] = g_cand[idx];
    }
    if (tid < NN / 32) colbits[tid] = g_colbits[tid];
    {
        u64 c0 = g_cand[tid * TCAND];
        u32 key = (u32)(c0 >> 32);
        u32 col = (u32)c0 & 0xFFFu;
        sheads[tid] = key ? packHead(key, ((u32)tid << 12) | col) : 0ull;
    }
    hptr[tid] = 1;
    int myCont = cont[tid];
    out_act[tid] = myCont ? (float)prev[tid] : -1.0f;
    int K = __syncthreads_count(myCont == 0);
    if (tid == 0) Ksh = K;
    __syncthreads();
    if (tid >= 32) return;     // only warp 0 continues

    const int lane = tid;
    const int base = lane * 32;
    const int K2 = Ksh;
    const ulonglong2* sp = (const ulonglong2*)(sheads + base);

    // group maxes: lane's 32 rows as 8 groups of 4
    u64 G0, G1, G2, G3, G4, G5, G6, G7;
    {
        ulonglong2 x, y;
        #define LOADG(G, g) \
            x = sp[(g)*2]; y = sp[(g)*2+1]; \
            G = u64max(u64max(x.x, x.y), u64max(y.x, y.y));
        LOADG(G0,0) LOADG(G1,1) LOADG(G2,2) LOADG(G3,3)
        LOADG(G4,4) LOADG(G5,5) LOADG(G6,6) LOADG(G7,7)
        #undef LOADG
    }
    u64 p1 = TREEMAX8(G0, G1, G2, G3, G4, G5, G6, G7);

    int assigned = 0;
    int guard = 0;

    while (assigned < K2) {
        if (++guard > 16384) break;                 // safety (never hit)
        u32 k1v = (u32)(p1 >> 23);
        u32 mx = __reduce_max_sync(FULLMASK, k1v);
        if (mx == 0) break;
        u32 cnd = (k1v == mx) ? (u32)(p1 & 0x7FFFFFu) : 0u;  // nonzero iff live
        u32 sel = __reduce_max_sync(FULLMASK, cnd);
        u32 rc = 0x400000u - sel;                   // all lanes know (row,col)
        int a = (int)(rc >> 12);
        int t = (int)(rc & 0xFFFu);
        const int gbase = a & ~3;                   // group-of-4 start row
        const int g = (a >> 2) & 7;
        const bool own = (lane == (a >> 5));
        u32 wi = (u32)t >> 5, bit = 1u << (t & 31);
        u32 w = colbits[wi];                        // broadcast LDS, uniform

        if (!((w >> (t & 31)) & 1u)) {
            // ============ COMMIT: fully replicated, no divergence ==========
            colbits[wi] = w | bit;                  // all lanes, same addr/val
            sheads[a] = 0ull;                       // all lanes, same addr/val
            out_act[a] = (float)t;                  // all lanes, same addr/val
            assigned++;
        } else {
            // ============ STALE (rare, ~35/run): divergent + syncwarp ======
            int need = 0;
            u64 np = 0ull;
            if (own) {
                int p = hptr[a];
                while (p < TCAND) {
                    u64 cd = scand[(a << 2) + p];
                    p++;
                    u32 kk = (u32)(cd >> 32);
                    if (!kk) { p = TCAND; break; }
                    u32 cc = (u32)cd & 0xFFFu;
                    if (!((colbits[cc >> 5] >> (cc & 31)) & 1u)) {
                        np = packHead(kk, ((u32)a << 12) | cc);
                        break;
                    }
                }
                hptr[a] = (unsigned char)p;
                if (np) sheads[a] = np;
                else    need = 1;
            }
            need = __shfl_sync(FULLMASK, need, a >> 5);
            if (need) {
                // warp-cooperative exact rescan of row a
                const float4* rp = (const float4*)(scores + (size_t)a * NN);
                u32 bk = 0, bc = 0xFFFu;
                #pragma unroll 4
                for (int q = 0; q < 32; q++) {
                    int f = lane + q * 32;
                    float4 vv = rp[f];
                    int c0i = f * 4;
                    float arr[4] = { vv.x, vv.y, vv.z, vv.w };
                    #pragma unroll
                    for (int j = 0; j < 4; j++) {
                        int cc = c0i + j;
                        if (!((colbits[cc >> 5] >> (cc & 31)) & 1u)) {
                            u32 kk = orderKey(arr[j]);
                            if (kk > bk) { bk = kk; bc = (u32)cc; }
                        }
                    }
                }
                u32 mk = __reduce_max_sync(FULLMASK, bk);
                u32 pc = (bk == mk) ? (0x1000u - bc) : 0u;
                u32 ps = __reduce_max_sync(FULLMASK, pc);
                if (own) {
                    sheads[a] = mk ? packHead(mk, ((u32)a << 12) | (0x1000u - ps)) : 0ull;
                    hptr[a] = TCAND;      // future pops rescan again
                }
            }
            __syncwarp(FULLMASK);  // owner's sheads[a] visible to all lanes
        }

        // ---- shared tail: broadcast reload of owner's group; SEL update ---
        {
            ulonglong2 x = *(const ulonglong2*)(sheads + gbase);      // bcast
            ulonglong2 y = *(const ulonglong2*)(sheads + gbase + 2);  // bcast
            u64 ng = u64max(u64max(x.x, x.y), u64max(y.x, y.y));
            switch (g) {   // uniform switch; predicated SEL inside
                case 0: G0 = own ? ng : G0; break;
                case 1: G1 = own ? ng : G1; break;
                case 2: G2 = own ? ng : G2; break;
                case 3: G3 = own ? ng : G3; break;
                case 4: G4 = own ? ng : G4; break;
                case 5: G5 = own ? ng : G5; break;
                case 6: G6 = own ? ng : G6; break;
                default: G7 = own ? ng : G7; break;
            }
            p1 = TREEMAX8(G0, G1, G2, G3, G4, G5, G6, G7);
        }
    }
}

// ---------------- launch ---------------------------------------------------
extern "C" void kernel_launch(void* const* d_in, const int* in_sizes, int n_in,
                              void* d_out, int out_size) {
    const float* scores = (const float*)d_in[0];
    const int*   cont   = (const int*)d_in[1];
    const int*   prev   = (const int*)d_in[2];
    float* out = (float*)d_out;      // [0..1023] actions, [1024..] policy

    k0_colhit<<<1, 1024>>>(cont, prev);
    k1_row<<<MM, 256>>>(scores, cont);
    k2_global<<<1, 1024>>>();
    k4_policy<<<2048, 256>>>(scores, out + MM);
    k5_assign<<<1, 1024>>>(scores, cont, prev, out);
}

// round 7
// speedup vs baseline: 3.2988x; 1.5403x over previous
#include <cuda_runtime.h>
#include <cstdint>

#define MM 1024
#define NN 4096
#define TCAND 4
#define FULLMASK 0xffffffffu

typedef unsigned int       u32;
typedef unsigned long long u64;

// ---------------- device scratch (no allocations allowed) ----------------
__device__ int   g_colhit[NN];
__device__ u32   g_colbits[NN / 32];
__device__ float g_rowmax[MM];
__device__ float g_rowsum[MM];
__device__ u64   g_cand[MM * TCAND];   // per-row top-4: key<<32 | col
__device__ float g_gmax;
__device__ float g_gsum;

// Monotonic float -> uint32 ordering key (nonzero for all real floats).
__device__ __forceinline__ u32 orderKey(float v) {
    u32 b = __float_as_uint(v);
    return (b & 0x80000000u) ? ~b : (b | 0x80000000u);
}

// Packed head: key high, inverted flat index (row<<12|col) low 23 bits.
// u64 max == (max key, then smallest flat index) — exact reference tie-break.
__device__ __forceinline__ u64 packHead(u32 key, u32 rc) {
    return ((u64)key << 23) | (u64)(0x400000u - rc);
}

__device__ __forceinline__ u64 u64max(u64 a, u64 b) { return a > b ? a : b; }
__device__ __forceinline__ u64 u64min(u64 a, u64 b) { return a < b ? a : b; }

// ---------------- K0: column-hit mask (bytes + bitmask) ------------------
__global__ void k0_colhit(const int* __restrict__ cont, const int* __restrict__ prev) {
    int tid = threadIdx.x;                 // 1024 threads
    #pragma unroll
    for (int k = 0; k < 4; k++) g_colhit[tid + k * 1024] = 0;
    if (tid < NN / 32) g_colbits[tid] = 0;
    __syncthreads();
    if (cont[tid]) {
        int c = prev[tid];
        g_colhit[c] = 1;                                  // benign races
        atomicOr(&g_colbits[c >> 5], 1u << (c & 31));
    }
}

// ---------------- K1: per-row rowmax, sumexp, top-4 masked candidates ----
__global__ void __launch_bounds__(256) k1_row(const float* __restrict__ scores,
                                              const int* __restrict__ cont) {
    const int r = blockIdx.x, tid = threadIdx.x, lane = tid & 31, warp = tid >> 5;
    __shared__ float wf[8];
    __shared__ u32   wk[8], wc[8];
    __shared__ float s_bcast;
    __shared__ u32   s_wincol;

    const float4* row = (const float4*)(scores + (size_t)r * NN);
    const bool isCont = (cont[r] != 0);

    float vals[16];
    int   fidx[4];
    #pragma unroll
    for (int k = 0; k < 4; k++) {
        int f = tid + k * 256; fidx[k] = f;
        float4 v = row[f];
        vals[k * 4 + 0] = v.x; vals[k * 4 + 1] = v.y;
        vals[k * 4 + 2] = v.z; vals[k * 4 + 3] = v.w;
    }
    u32 freeMask = 0;
    if (!isCont) {
        #pragma unroll
        for (int k = 0; k < 4; k++) {
            int4 h = ((const int4*)g_colhit)[fidx[k]];
            if (!h.x) freeMask |= 1u << (k * 4 + 0);
            if (!h.y) freeMask |= 1u << (k * 4 + 1);
            if (!h.z) freeMask |= 1u << (k * 4 + 2);
            if (!h.w) freeMask |= 1u << (k * 4 + 3);
        }
    }

    // ---- raw row max ----
    float m = vals[0];
    #pragma unroll
    for (int e = 1; e < 16; e++) m = fmaxf(m, vals[e]);
    #pragma unroll
    for (int off = 16; off; off >>= 1) m = fmaxf(m, __shfl_xor_sync(FULLMASK, m, off));
    if (lane == 0) wf[warp] = m;
    __syncthreads();
    if (warp == 0) {
        float t = (lane < 8) ? wf[lane] : -3.4e38f;
        #pragma unroll
        for (int off = 4; off; off >>= 1) t = fmaxf(t, __shfl_xor_sync(FULLMASK, t, off));
        if (lane == 0) { s_bcast = t; g_rowmax[r] = t; }
    }
    __syncthreads();
    float rowmax = s_bcast;

    // ---- row sumexp (stable at rowmax) ----
    float s = 0.f;
    #pragma unroll
    for (int e = 0; e < 16; e++) s += __expf(vals[e] - rowmax);
    #pragma unroll
    for (int off = 16; off; off >>= 1) s += __shfl_xor_sync(FULLMASK, s, off);
    __syncthreads();
    if (lane == 0) wf[warp] = s;
    __syncthreads();
    if (warp == 0) {
        float t = (lane < 8) ? wf[lane] : 0.f;
        #pragma unroll
        for (int off = 4; off; off >>= 1) t += __shfl_xor_sync(FULLMASK, t, off);
        if (lane == 0) g_rowsum[r] = t;
    }

    // ---- 4 rounds of masked argmax -> candidate list ----
    for (int round = 0; round < TCAND; round++) {
        u32 bk = 0, bc = 0xFFFFFFFFu;
        #pragma unroll
        for (int k = 0; k < 4; k++) {
            #pragma unroll
            for (int j = 0; j < 4; j++) {
                int e = k * 4 + j;
                if (freeMask & (1u << e)) {
                    u32 kk = orderKey(vals[e]);
                    if (kk > bk) { bk = kk; bc = (u32)(fidx[k] * 4 + j); }
                }
            }
        }
        #pragma unroll
        for (int off = 16; off; off >>= 1) {
            u32 ok = __shfl_xor_sync(FULLMASK, bk, off);
            u32 oc = __shfl_xor_sync(FULLMASK, bc, off);
            if (ok > bk || (ok == bk && oc < bc)) { bk = ok; bc = oc; }
        }
        if (lane == 0) { wk[warp] = bk; wc[warp] = bc; }
        __syncthreads();
        if (warp == 0) {
            u32 tk = (lane < 8) ? wk[lane] : 0u;
            u32 tc = (lane < 8) ? wc[lane] : 0xFFFFFFFFu;
            #pragma unroll
            for (int off = 4; off; off >>= 1) {
                u32 ok = __shfl_xor_sync(FULLMASK, tk, off);
                u32 oc = __shfl_xor_sync(FULLMASK, tc, off);
                if (ok > tk || (ok == tk && oc < tc)) { tk = ok; tc = oc; }
            }
            if (lane == 0) {
                g_cand[r * TCAND + round] = tk ? (((u64)tk << 32) | tc) : 0ull;
                s_wincol = tk ? tc : 0xFFFFFFFFu;
            }
        }
        __syncthreads();
        u32 cw = s_wincol;
        if (cw != 0xFFFFFFFFu) {
            int f = (int)(cw >> 2);
            if ((f & 255) == tid) {
                int k = f >> 8, j = (int)(cw & 3u);
                freeMask &= ~(1u << (k * 4 + j));
            }
        }
        __syncthreads();
    }
}

// ---------------- K2: global max + global sum (from row stats) -----------
__global__ void __launch_bounds__(1024) k2_global() {
    int tid = threadIdx.x, lane = tid & 31, warp = tid >> 5;
    __shared__ float w[32];
    __shared__ float s_gm;
    float rm = g_rowmax[tid];
    float m = rm;
    #pragma unroll
    for (int off = 16; off; off >>= 1) m = fmaxf(m, __shfl_xor_sync(FULLMASK, m, off));
    if (lane == 0) w[warp] = m;
    __syncthreads();
    if (warp == 0) {
        float t = w[lane];
        #pragma unroll
        for (int off = 16; off; off >>= 1) t = fmaxf(t, __shfl_xor_sync(FULLMASK, t, off));
        if (lane == 0) s_gm = t;
    }
    __syncthreads();
    float gm = s_gm;
    float s = g_rowsum[tid] * __expf(rm - gm);
    #pragma unroll
    for (int off = 16; off; off >>= 1) s += __shfl_xor_sync(FULLMASK, s, off);
    __syncthreads();
    if (lane == 0) w[warp] = s;
    __syncthreads();
    if (warp == 0) {
        float t = w[lane];
        #pragma unroll
        for (int off = 16; off; off >>= 1) t += __shfl_xor_sync(FULLMASK, t, off);
        if (lane == 0) { g_gmax = gm; g_gsum = t; }
    }
}

// ---------------- K4: write normalized policy ----------------------------
__global__ void __launch_bounds__(256) k4_policy(const float* __restrict__ scores,
                                                 float* __restrict__ out_pol) {
    const float gm = g_gmax;
    const float inv = 1.0f / g_gsum;
    int i = blockIdx.x * 256 + threadIdx.x;
    const float4* p = (const float4*)scores;
    float4* o = (float4*)out_pol;
    float4 a = p[i];
    float4 b = p[i + 524288];
    float4 ra, rb;
    ra.x = __expf(a.x - gm) * inv; ra.y = __expf(a.y - gm) * inv;
    ra.z = __expf(a.z - gm) * inv; ra.w = __expf(a.w - gm) * inv;
    rb.x = __expf(b.x - gm) * inv; rb.y = __expf(b.y - gm) * inv;
    rb.z = __expf(b.z - gm) * inv; rb.w = __expf(b.w - gm) * inv;
    o[i] = ra;
    o[i + 524288] = rb;
}

// ---------------- K5: greedy assignment — multi-commit batches -----------
// Lane L owns rows [32L, 32L+32) as 4 groups of 8. Per-group top-2 cached
// in smem (sgt); lane-level (p1, p2) in registers. A batch commits every
// head strictly above S = max(all p2, stale/dup p1) — exact greedy prefix.

// top-2 of a group of 8 heads
__device__ __forceinline__ void top2of8(const ulonglong2* gp, u64& m, u64& s) {
    ulonglong2 q0 = gp[0], q1 = gp[1], q2 = gp[2], q3 = gp[3];
    u64 m0 = u64max(q0.x, q0.y), s0 = u64min(q0.x, q0.y);
    u64 m1 = u64max(q1.x, q1.y), s1 = u64min(q1.x, q1.y);
    u64 m2 = u64max(q2.x, q2.y), s2 = u64min(q2.x, q2.y);
    u64 m3 = u64max(q3.x, q3.y), s3 = u64min(q3.x, q3.y);
    u64 ma = u64max(m0, m1), sa = u64max(u64min(m0, m1), (m0 > m1) ? s0 : s1);
    u64 mb = u64max(m2, m3), sb = u64max(u64min(m2, m3), (m2 > m3) ? s2 : s3);
    m = u64max(ma, mb);
    s = u64max(u64min(ma, mb), (ma > mb) ? sa : sb);
}

__global__ void __launch_bounds__(1024, 1) k5_assign(
        const float* __restrict__ scores,
        const int* __restrict__ cont,
        const int* __restrict__ prev,
        float* __restrict__ out_act) {
    __shared__ __align__(16) u64 sheads[MM];          // 8KB packed heads
    __shared__ __align__(16) u64 scand[MM * TCAND];   // 32KB candidate lists
    __shared__ __align__(16) u64 sgt1[32 * 4];        // 1KB group top-1
    __shared__ __align__(16) u64 sgt2[32 * 4];        // 1KB group top-2
    __shared__ u32 colbits[NN / 32];                  // 512B col bitmask
    __shared__ unsigned char hptr[MM];                // 1KB next cand index
    __shared__ int Ksh;

    const int tid = threadIdx.x;

    // -------- prologue: full block builds shared state --------
    #pragma unroll
    for (int k = 0; k < TCAND; k++) {
        int idx = tid + k * 1024;
        scand[idx] = g_cand[idx];
    }
    if (tid < NN / 32) colbits[tid] = g_colbits[tid];
    {
        u64 c0 = g_cand[tid * TCAND];
        u32 key = (u32)(c0 >> 32);
        u32 col = (u32)c0 & 0xFFFu;
        sheads[tid] = key ? packHead(key, ((u32)tid << 12) | col) : 0ull;
    }
    hptr[tid] = 1;
    int myCont = cont[tid];
    out_act[tid] = myCont ? (float)prev[tid] : -1.0f;
    int K = __syncthreads_count(myCont == 0);
    if (tid == 0) Ksh = K;
    __syncthreads();
    if (tid >= 32) return;     // only warp 0 continues

    const int lane = tid;
    const int base = lane * 32;
    const int K2 = Ksh;

    // build group top-2 cache + lane (p1,p2)
    u64 p1, p2;
    {
        #pragma unroll
        for (int g = 0; g < 4; g++) {
            u64 m, s;
            top2of8((const ulonglong2*)(sheads + base + g * 8), m, s);
            sgt1[(lane << 2) + g] = m;
            sgt2[(lane << 2) + g] = s;
        }
    }
    {
        const ulonglong2* t1p = (const ulonglong2*)(sgt1 + (lane << 2));
        const ulonglong2* t2p = (const ulonglong2*)(sgt2 + (lane << 2));
        ulonglong2 M01 = t1p[0], M23 = t1p[1], S01 = t2p[0], S23 = t2p[1];
        u64 ma = u64max(M01.x, M01.y);
        u64 sa = u64max(u64min(M01.x, M01.y), (M01.x > M01.y) ? S01.x : S01.y);
        u64 mb = u64max(M23.x, M23.y);
        u64 sb = u64max(u64min(M23.x, M23.y), (M23.x > M23.y) ? S23.x : S23.y);
        p1 = u64max(ma, mb);
        p2 = u64max(u64min(ma, mb), (ma > mb) ? sa : sb);
    }

    int assigned = 0;
    int guard = 0;

    while (assigned < K2) {
        if (++guard > 16384) break;                  // safety (never hit)

        u32 key = (u32)(p1 >> 23);
        u32 mk = __reduce_max_sync(FULLMASK, key);
        if (!mk) break;
        bool live = (key != 0u);
        u32 lo = (u32)p1 & 0x7FFFFFu;
        u32 rc = 0x400000u - lo;
        int a = (int)(rc >> 12), t = (int)(rc & 0xFFFu);
        u32 wi = (u32)t >> 5, bit = 1u << (t & 31);
        bool stale = live && ((colbits[wi] >> (t & 31)) & 1u);
        u32 colkey = live ? (u32)t : (0x2000u + (u32)lane);
        u32 grp = __match_any_sync(FULLMASK, colkey);
        bool dup = live && ((grp & (grp - 1u)) != 0u);

        // cutoff S = max(all p2, stale/dup p1)
        u64 contrib = (live && (stale || dup)) ? p1 : p2;   // p1 >= p2
        u32 chi = (u32)(contrib >> 23);
        u32 sh = __reduce_max_sync(FULLMASK, chi);
        u32 cl = (chi == sh) ? ((u32)contrib & 0x7FFFFFu) : 0u;
        u32 sl = __reduce_max_sync(FULLMASK, cl);
        u64 S = ((u64)sh << 23) | sl;

        bool commit = live && !stale && !dup && (p1 > S);
        u32 cb = __ballot_sync(FULLMASK, commit);

        bool chg = false; int cg = 0; int rsRow = -1;

        if (cb) {
            // ========= parallel commits (distinct rows, distinct cols) ====
            if (commit) {
                atomicOr(&colbits[wi], bit);     // word may be shared
                out_act[a] = (float)t;
                sheads[a] = 0ull;
                chg = true; cg = (a >> 3) & 3;
            }
            assigned += __popc(cb);
            __syncwarp(FULLMASK);
            // parallel pops for stale lanes (against updated colbits)
            if (stale) {
                int p = hptr[a]; u64 np = 0ull;
                if (p >= TCAND) rsRow = a;
                else {
                    while (p < TCAND) {
                        u64 cd = scand[(a << 2) + p]; p++;
                        u32 kk = (u32)(cd >> 32);
                        if (!kk) { p = TCAND; break; }
                        u32 cc = (u32)cd & 0xFFFu;
                        if (!((colbits[cc >> 5] >> (cc & 31)) & 1u)) {
                            np = packHead(kk, ((u32)a << 12) | cc); break;
                        }
                    }
                    hptr[a] = (unsigned char)p;
                    if (np) sheads[a] = np; else rsRow = a;
                }
                chg = true; cg = (a >> 3) & 3;
            }
        } else {
            // ========= fallback: single commit/pop of global top ==========
            u32 cnd = (key == mk) ? lo : 0u;
            u32 sel = __reduce_max_sync(FULLMASK, cnd);
            u32 rc2 = 0x400000u - sel;
            int a2 = (int)(rc2 >> 12), t2 = (int)(rc2 & 0xFFFu);
            u32 wi2 = (u32)t2 >> 5, b2 = 1u << (t2 & 31);
            bool own = (lane == (a2 >> 5));
            u32 w = colbits[wi2];                          // uniform
            if (!((w >> (t2 & 31)) & 1u)) {
                colbits[wi2] = w | b2;                     // replicated store
                out_act[a2] = (float)t2;
                sheads[a2] = 0ull;
                assigned++;
                if (own) { chg = true; cg = (a2 >> 3) & 3; }
            } else {
                if (own) {
                    int p = hptr[a2]; u64 np = 0ull;
                    if (p >= TCAND) rsRow = a2;
                    else {
                        while (p < TCAND) {
                            u64 cd = scand[(a2 << 2) + p]; p++;
                            u32 kk = (u32)(cd >> 32);
                            if (!kk) { p = TCAND; break; }
                            u32 cc = (u32)cd & 0xFFFu;
                            if (!((colbits[cc >> 5] >> (cc & 31)) & 1u)) {
                                np = packHead(kk, ((u32)a2 << 12) | cc); break;
                            }
                        }
                        hptr[a2] = (unsigned char)p;
                        if (np) sheads[a2] = np; else rsRow = a2;
                    }
                    chg = true; cg = (a2 >> 3) & 3;
                }
            }
            __syncwarp(FULLMASK);
        }

        // ========= rare: warp-cooperative full rescans =========
        for (;;) {
            u32 rb = __ballot_sync(FULLMASK, rsRow >= 0);
            if (!rb) break;
            int ln = __ffs((int)rb) - 1;
            int ra = __shfl_sync(FULLMASK, rsRow, ln);
            const float4* rp = (const float4*)(scores + (size_t)ra * NN);
            u32 bk = 0, bc = 0xFFFu;
            #pragma unroll 4
            for (int q = 0; q < 32; q++) {
                int f = lane + q * 32;
                float4 vv = rp[f];
                int c0i = f * 4;
                float arr[4] = { vv.x, vv.y, vv.z, vv.w };
                #pragma unroll
                for (int j = 0; j < 4; j++) {
                    int cc = c0i + j;
                    if (!((colbits[cc >> 5] >> (cc & 31)) & 1u)) {
                        u32 kk = orderKey(arr[j]);
                        if (kk > bk) { bk = kk; bc = (u32)cc; }
                    }
                }
            }
            u32 mk2 = __reduce_max_sync(FULLMASK, bk);
            u32 pc = (bk == mk2) ? (0x1000u - bc) : 0u;
            u32 ps = __reduce_max_sync(FULLMASK, pc);
            if (lane == ln) {
                sheads[ra] = mk2 ? packHead(mk2, ((u32)ra << 12) | (0x1000u - ps)) : 0ull;
                hptr[ra] = TCAND;
                rsRow = -1;
            }
        }
        __syncwarp(FULLMASK);

        // ========= tail: refresh changed group + lane (p1,p2) =========
        {
            int g = cg;                     // 0 if !chg (harmless reload)
            u64 m, s;
            top2of8((const ulonglong2*)(sheads + base + g * 8), m, s);
            if (chg) {
                sgt1[(lane << 2) + g] = m;
                sgt2[(lane << 2) + g] = s;
            }
            const ulonglong2* t1p = (const ulonglong2*)(sgt1 + (lane << 2));
            const ulonglong2* t2p = (const ulonglong2*)(sgt2 + (lane << 2));
            ulonglong2 M01 = t1p[0], M23 = t1p[1], S01 = t2p[0], S23 = t2p[1];
            u64 ma = u64max(M01.x, M01.y);
            u64 sa = u64max(u64min(M01.x, M01.y), (M01.x > M01.y) ? S01.x : S01.y);
            u64 mb = u64max(M23.x, M23.y);
            u64 sb = u64max(u64min(M23.x, M23.y), (M23.x > M23.y) ? S23.x : S23.y);
            p1 = u64max(ma, mb);
            p2 = u64max(u64min(ma, mb), (ma > mb) ? sa : sb);
        }
    }
}

// ---------------- launch ---------------------------------------------------
extern "C" void kernel_launch(void* const* d_in, const int* in_sizes, int n_in,
                              void* d_out, int out_size) {
    const float* scores = (const float*)d_in[0];
    const int*   cont   = (const int*)d_in[1];
    const int*   prev   = (const int*)d_in[2];
    float* out = (float*)d_out;      // [0..1023] actions, [1024..] policy

    k0_colhit<<<1, 1024>>>(cont, prev);
    k1_row<<<MM, 256>>>(scores, cont);
    k2_global<<<1, 1024>>>();
    k4_policy<<<2048, 256>>>(scores, out + MM);
    k5_assign<<<1, 1024>>>(scores, cont, prev, out);
}

// round 8
// speedup vs baseline: 3.7214x; 1.1281x over previous
#include <cuda_runtime.h>
#include <cstdint>

#define MM 1024
#define NN 4096
#define TCAND 4
#define FULLMASK 0xffffffffu

typedef unsigned int       u32;
typedef unsigned long long u64;

// ---------------- device scratch (no allocations allowed) ----------------
__device__ int   g_colhit[NN];
__device__ u32   g_colbits[NN / 32];
__device__ float g_rowmax[MM];
__device__ float g_rowsum[MM];
__device__ u64   g_cand[MM * TCAND];   // per-row top-4: key<<32 | col
__device__ float g_gmax;
__device__ float g_gsum;

// Monotonic float -> uint32 ordering key (nonzero for all real floats).
__device__ __forceinline__ u32 orderKey(float v) {
    u32 b = __float_as_uint(v);
    return (b & 0x80000000u) ? ~b : (b | 0x80000000u);
}

// Packed head: key high, inverted flat index (row<<12|col) low 23 bits.
// u64 max == (max key, then smallest flat index) — exact reference tie-break.
__device__ __forceinline__ u64 packHead(u32 key, u32 rc) {
    return ((u64)key << 23) | (u64)(0x400000u - rc);
}

__device__ __forceinline__ u64 u64max(u64 a, u64 b) { return a > b ? a : b; }

// insert into descending top-3 (x1 >= x2 >= x3)
#define INS3(h) do { u64 _h = (h); \
    if (_h > x2) { if (_h > x1) { x3 = x2; x2 = x1; x1 = _h; } \
                   else         { x3 = x2; x2 = _h; } } \
    else if (_h > x3) x3 = _h; } while (0)

// ---------------- K0: column-hit mask (bytes + bitmask) ------------------
__global__ void k0_colhit(const int* __restrict__ cont, const int* __restrict__ prev) {
    int tid = threadIdx.x;                 // 1024 threads
    #pragma unroll
    for (int k = 0; k < 4; k++) g_colhit[tid + k * 1024] = 0;
    if (tid < NN / 32) g_colbits[tid] = 0;
    __syncthreads();
    if (cont[tid]) {
        int c = prev[tid];
        g_colhit[c] = 1;                                  // benign races
        atomicOr(&g_colbits[c >> 5], 1u << (c & 31));
    }
}

// ---------------- K1: per-row rowmax, sumexp, top-4 masked candidates ----
__global__ void __launch_bounds__(256) k1_row(const float* __restrict__ scores,
                                              const int* __restrict__ cont) {
    const int r = blockIdx.x, tid = threadIdx.x, lane = tid & 31, warp = tid >> 5;
    __shared__ float wf[8];
    __shared__ u32   wk[8], wc[8];
    __shared__ float s_bcast;
    __shared__ u32   s_wincol;

    const float4* row = (const float4*)(scores + (size_t)r * NN);
    const bool isCont = (cont[r] != 0);

    float vals[16];
    int   fidx[4];
    #pragma unroll
    for (int k = 0; k < 4; k++) {
        int f = tid + k * 256; fidx[k] = f;
        float4 v = row[f];
        vals[k * 4 + 0] = v.x; vals[k * 4 + 1] = v.y;
        vals[k * 4 + 2] = v.z; vals[k * 4 + 3] = v.w;
    }
    u32 freeMask = 0;
    if (!isCont) {
        #pragma unroll
        for (int k = 0; k < 4; k++) {
            int4 h = ((const int4*)g_colhit)[fidx[k]];
            if (!h.x) freeMask |= 1u << (k * 4 + 0);
            if (!h.y) freeMask |= 1u << (k * 4 + 1);
            if (!h.z) freeMask |= 1u << (k * 4 + 2);
            if (!h.w) freeMask |= 1u << (k * 4 + 3);
        }
    }

    // ---- raw row max ----
    float m = vals[0];
    #pragma unroll
    for (int e = 1; e < 16; e++) m = fmaxf(m, vals[e]);
    #pragma unroll
    for (int off = 16; off; off >>= 1) m = fmaxf(m, __shfl_xor_sync(FULLMASK, m, off));
    if (lane == 0) wf[warp] = m;
    __syncthreads();
    if (warp == 0) {
        float t = (lane < 8) ? wf[lane] : -3.4e38f;
        #pragma unroll
        for (int off = 4; off; off >>= 1) t = fmaxf(t, __shfl_xor_sync(FULLMASK, t, off));
        if (lane == 0) { s_bcast = t; g_rowmax[r] = t; }
    }
    __syncthreads();
    float rowmax = s_bcast;

    // ---- row sumexp (stable at rowmax) ----
    float s = 0.f;
    #pragma unroll
    for (int e = 0; e < 16; e++) s += __expf(vals[e] - rowmax);
    #pragma unroll
    for (int off = 16; off; off >>= 1) s += __shfl_xor_sync(FULLMASK, s, off);
    __syncthreads();
    if (lane == 0) wf[warp] = s;
    __syncthreads();
    if (warp == 0) {
        float t = (lane < 8) ? wf[lane] : 0.f;
        #pragma unroll
        for (int off = 4; off; off >>= 1) t += __shfl_xor_sync(FULLMASK, t, off);
        if (lane == 0) g_rowsum[r] = t;
    }

    // ---- 4 rounds of masked argmax -> candidate list ----
    for (int round = 0; round < TCAND; round++) {
        u32 bk = 0, bc = 0xFFFFFFFFu;
        #pragma unroll
        for (int k = 0; k < 4; k++) {
            #pragma unroll
            for (int j = 0; j < 4; j++) {
                int e = k * 4 + j;
                if (freeMask & (1u << e)) {
                    u32 kk = orderKey(vals[e]);
                    if (kk > bk) { bk = kk; bc = (u32)(fidx[k] * 4 + j); }
                }
            }
        }
        #pragma unroll
        for (int off = 16; off; off >>= 1) {
            u32 ok = __shfl_xor_sync(FULLMASK, bk, off);
            u32 oc = __shfl_xor_sync(FULLMASK, bc, off);
            if (ok > bk || (ok == bk && oc < bc)) { bk = ok; bc = oc; }
        }
        if (lane == 0) { wk[warp] = bk; wc[warp] = bc; }
        __syncthreads();
        if (warp == 0) {
            u32 tk = (lane < 8) ? wk[lane] : 0u;
            u32 tc = (lane < 8) ? wc[lane] : 0xFFFFFFFFu;
            #pragma unroll
            for (int off = 4; off; off >>= 1) {
                u32 ok = __shfl_xor_sync(FULLMASK, tk, off);
                u32 oc = __shfl_xor_sync(FULLMASK, tc, off);
                if (ok > tk || (ok == tk && oc < tc)) { tk = ok; tc = oc; }
            }
            if (lane == 0) {
                g_cand[r * TCAND + round] = tk ? (((u64)tk << 32) | tc) : 0ull;
                s_wincol = tk ? tc : 0xFFFFFFFFu;
            }
        }
        __syncthreads();
        u32 cw = s_wincol;
        if (cw != 0xFFFFFFFFu) {
            int f = (int)(cw >> 2);
            if ((f & 255) == tid) {
                int k = f >> 8, j = (int)(cw & 3u);
                freeMask &= ~(1u << (k * 4 + j));
            }
        }
        __syncthreads();
    }
}

// ---------------- K2: global max + global sum (from row stats) -----------
__global__ void __launch_bounds__(1024) k2_global() {
    int tid = threadIdx.x, lane = tid & 31, warp = tid >> 5;
    __shared__ float w[32];
    __shared__ float s_gm;
    float rm = g_rowmax[tid];
    float m = rm;
    #pragma unroll
    for (int off = 16; off; off >>= 1) m = fmaxf(m, __shfl_xor_sync(FULLMASK, m, off));
    if (lane == 0) w[warp] = m;
    __syncthreads();
    if (warp == 0) {
        float t = w[lane];
        #pragma unroll
        for (int off = 16; off; off >>= 1) t = fmaxf(t, __shfl_xor_sync(FULLMASK, t, off));
        if (lane == 0) s_gm = t;
    }
    __syncthreads();
    float gm = s_gm;
    float s = g_rowsum[tid] * __expf(rm - gm);
    #pragma unroll
    for (int off = 16; off; off >>= 1) s += __shfl_xor_sync(FULLMASK, s, off);
    __syncthreads();
    if (lane == 0) w[warp] = s;
    __syncthreads();
    if (warp == 0) {
        float t = w[lane];
        #pragma unroll
        for (int off = 16; off; off >>= 1) t += __shfl_xor_sync(FULLMASK, t, off);
        if (lane == 0) { g_gmax = gm; g_gsum = t; }
    }
}

// ---------------- K45: fused policy write + greedy assignment ------------
// blocks 0..511: policy (1024 thr, 2 float4 each). block 512: assignment.
// Dynamic smem layout (assignment block only):
#define OFF_SHEADS 0
#define OFF_SCAND  8192
#define OFF_CLAIM  40960
#define OFF_SGT    57344
#define OFF_COLB   60416
#define OFF_HPTR   60928
#define OFF_MISC   61952
#define DSMEM      62464

__global__ void __launch_bounds__(1024, 1) k45_fused(
        const float* __restrict__ scores,
        const int* __restrict__ cont,
        const int* __restrict__ prev,
        float* __restrict__ out) {
    extern __shared__ char dyn[];
    const int tid = threadIdx.x;

    if (blockIdx.x < 512) {
        // ================= policy =================
        const float gm = g_gmax;
        const float inv = 1.0f / g_gsum;
        int i = blockIdx.x * 1024 + tid;
        const float4* p = (const float4*)scores;
        float4* o = (float4*)(out + MM);
        float4 a = p[i];
        float4 b = p[i + 524288];
        float4 ra, rb;
        ra.x = __expf(a.x - gm) * inv; ra.y = __expf(a.y - gm) * inv;
        ra.z = __expf(a.z - gm) * inv; ra.w = __expf(a.w - gm) * inv;
        rb.x = __expf(b.x - gm) * inv; rb.y = __expf(b.y - gm) * inv;
        rb.z = __expf(b.z - gm) * inv; rb.w = __expf(b.w - gm) * inv;
        o[i] = ra;
        o[i + 524288] = rb;
        return;
    }

    // ================= assignment (block 512) =================
    u64* sheads = (u64*)(dyn + OFF_SHEADS);
    u64* scand  = (u64*)(dyn + OFF_SCAND);
    u32* claimc = (u32*)(dyn + OFF_CLAIM);
    u64* sgt    = (u64*)(dyn + OFF_SGT);         // [0..127]=t1 [128..]=t2 [256..]=t3
    u32* colbits = (u32*)(dyn + OFF_COLB);
    unsigned char* hptr = (unsigned char*)(dyn + OFF_HPTR);
    int* misc = (int*)(dyn + OFF_MISC);
    float* out_act = out;

    // -------- prologue: full block builds shared state --------
    #pragma unroll
    for (int k = 0; k < TCAND; k++) {
        int idx = tid + k * 1024;
        scand[idx] = g_cand[idx];
        claimc[idx] = 0;
    }
    if (tid < NN / 32) colbits[tid] = g_colbits[tid];
    {
        u64 c0 = g_cand[tid * TCAND];
        u32 key = (u32)(c0 >> 32);
        u32 col = (u32)c0 & 0xFFFu;
        sheads[tid] = key ? packHead(key, ((u32)tid << 12) | col) : 0ull;
    }
    hptr[tid] = 1;
    int myCont = cont[tid];
    out_act[tid] = myCont ? (float)prev[tid] : -1.0f;
    int K = __syncthreads_count(myCont == 0);
    if (tid == 0) misc[0] = K;
    __syncthreads();
    if (tid >= 32) return;

    const int lane = tid;
    const int base = lane * 32;
    const int K2 = misc[0];

    // per-group top-3 cache + lane p1,p2,p3
    u64 p1, p2, p3;
    {
        #pragma unroll
        for (int g = 0; g < 4; g++) {
            u64 x1 = 0, x2 = 0, x3 = 0;
            const ulonglong2* gp = (const ulonglong2*)(sheads + base + g * 8);
            #pragma unroll
            for (int q = 0; q < 4; q++) { ulonglong2 hh = gp[q]; INS3(hh.x); INS3(hh.y); }
            sgt[(lane << 2) + g] = x1;
            sgt[128 + (lane << 2) + g] = x2;
            sgt[256 + (lane << 2) + g] = x3;
        }
        u64 x1 = 0, x2 = 0, x3 = 0;
        #pragma unroll
        for (int g = 0; g < 4; g++) {
            INS3(sgt[(lane << 2) + g]);
            INS3(sgt[128 + (lane << 2) + g]);
            INS3(sgt[256 + (lane << 2) + g]);
        }
        p1 = x1; p2 = x2; p3 = x3;
    }

    int assigned = 0;
    int guard = 0;

    while (assigned < K2) {
        if (++guard > 16384) break;                  // safety (never hit)

        // ---- candidates: lane's top-2 heads (distinct rows) ----
        bool l1 = (p1 != 0ull), l2 = (p2 != 0ull);
        u32 rc1 = 0x400000u - (u32)(p1 & 0x7FFFFFu);
        u32 rc2 = 0x400000u - (u32)(p2 & 0x7FFFFFu);
        int r1 = (int)(rc1 >> 12), c1 = (int)(rc1 & 0xFFFu);
        int r2 = (int)(rc2 >> 12), c2 = (int)(rc2 & 0xFFFu);

        // ---- stale at batch start ----
        bool s1 = l1 && ((colbits[c1 >> 5] >> (c1 & 31)) & 1u);
        bool s2 = l2 && ((colbits[c2 >> 5] >> (c2 & 31)) & 1u);

        // ---- dup detection among live offers ----
        if (l1 && !s1) atomicAdd(&claimc[c1], 1u);
        if (l2 && !s2) atomicAdd(&claimc[c2], 1u);
        __syncwarp(FULLMASK);
        bool d1 = l1 && !s1 && (claimc[c1] > 1u);
        bool d2 = l2 && !s2 && (claimc[c2] > 1u);
        __syncwarp(FULLMASK);
        if (l1 && !s1) claimc[c1] = 0;
        if (l2 && !s2) claimc[c2] = 0;

        // ---- cutoff S = max(hidden bound p3, stale/dup offer values) ----
        u64 contrib = p3;
        if (s1 || d1) contrib = u64max(contrib, p1);
        if (s2 || d2) contrib = u64max(contrib, p2);
        u32 chi = (u32)(contrib >> 32);
        u32 mh = __reduce_max_sync(FULLMASK, chi);
        u32 clo = (chi == mh) ? (u32)contrib : 0u;
        u32 ml = __reduce_max_sync(FULLMASK, clo);
        u64 S = ((u64)mh << 32) | ml;

        // ---- parallel commits ----
        bool k1c = l1 && !s1 && !d1 && (p1 > S);
        bool k2c = l2 && !s2 && !d2 && (p2 > S);
        if (k1c) { atomicOr(&colbits[c1 >> 5], 1u << (c1 & 31));
                   out_act[r1] = (float)c1; sheads[r1] = 0ull; }
        if (k2c) { atomicOr(&colbits[c2 >> 5], 1u << (c2 & 31));
                   out_act[r2] = (float)c2; sheads[r2] = 0ull; }
        u32 cb = __ballot_sync(FULLMASK, k1c) ;
        u32 cb2 = __ballot_sync(FULLMASK, k2c);
        assigned += __popc(cb) + __popc(cb2);
        __syncwarp(FULLMASK);

        // ---- fallback single-commit when batch was empty ----
        if (!(cb | cb2)) {
            u32 key = (u32)(p1 >> 23);
            u32 mk = __reduce_max_sync(FULLMASK, key);
            if (mk == 0) break;                       // nothing left (uniform)
            u32 cnd = (key == mk) ? (u32)(p1 & 0x7FFFFFu) : 0u;
            u32 sel = __reduce_max_sync(FULLMASK, cnd);
            u32 rcf = 0x400000u - sel;
            int af = (int)(rcf >> 12), tf = (int)(rcf & 0xFFFu);
            u32 w = colbits[tf >> 5];                 // uniform read
            if (!((w >> (tf & 31)) & 1u)) {
                colbits[tf >> 5] = w | (1u << (tf & 31));   // replicated
                out_act[af] = (float)tf;
                sheads[af] = 0ull;
                assigned++;
                if (lane == (af >> 5)) k1c = true;    // af == r1 for owner
            }
            // if stale: pop phase below handles it
        }

        // ---- pop phase: recheck my two offered rows vs updated colbits ----
        bool ch1 = k1c, ch2 = k2c;
        int rsA = -1, rsB = -1;
        if (l1) {
            u64 h = sheads[r1];
            if (h) {
                u32 hc = (0x400000u - (u32)(h & 0x7FFFFFu)) & 0xFFFu;
                if ((colbits[hc >> 5] >> (hc & 31)) & 1u) {
                    int p = hptr[r1]; u64 np = 0ull;
                    if (p < TCAND) {
                        while (p < TCAND) {
                            u64 cd = scand[(r1 << 2) + p]; p++;
                            u32 kk = (u32)(cd >> 32);
                            if (!kk) { p = TCAND; break; }
                            u32 cc = (u32)cd & 0xFFFu;
                            if (!((colbits[cc >> 5] >> (cc & 31)) & 1u)) {
                                np = packHead(kk, ((u32)r1 << 12) | cc); break;
                            }
                        }
                        hptr[r1] = (unsigned char)p;
                    }
                    if (np) sheads[r1] = np; else rsA = r1;
                    ch1 = true;
                }
            }
        }
        if (l2) {
            u64 h = sheads[r2];
            if (h) {
                u32 hc = (0x400000u - (u32)(h & 0x7FFFFFu)) & 0xFFFu;
                if ((colbits[hc >> 5] >> (hc & 31)) & 1u) {
                    int p = hptr[r2]; u64 np = 0ull;
                    if (p < TCAND) {
                        while (p < TCAND) {
                            u64 cd = scand[(r2 << 2) + p]; p++;
                            u32 kk = (u32)(cd >> 32);
                            if (!kk) { p = TCAND; break; }
                            u32 cc = (u32)cd & 0xFFFu;
                            if (!((colbits[cc >> 5] >> (cc & 31)) & 1u)) {
                                np = packHead(kk, ((u32)r2 << 12) | cc); break;
                            }
                        }
                        hptr[r2] = (unsigned char)p;
                    }
                    if (np) sheads[r2] = np; else rsB = r2;
                    ch2 = true;
                }
            }
        }

        // ---- rare: warp-cooperative exact rescans (list exhausted) ----
        for (;;) {
            int my = (rsA >= 0) ? rsA : rsB;
            u32 rb = __ballot_sync(FULLMASK, my >= 0);
            if (!rb) break;
            int ln = __ffs((int)rb) - 1;
            int ra = __shfl_sync(FULLMASK, my, ln);
            const float4* rp = (const float4*)(scores + (size_t)ra * NN);
            u32 bk = 0, bc = 0xFFFu;
            #pragma unroll 4
            for (int q = 0; q < 32; q++) {
                int f = lane + q * 32;
                float4 vv = rp[f];
                int c0i = f * 4;
                float arr[4] = { vv.x, vv.y, vv.z, vv.w };
                #pragma unroll
                for (int j = 0; j < 4; j++) {
                    int cc = c0i + j;
                    if (!((colbits[cc >> 5] >> (cc & 31)) & 1u)) {
                        u32 kk = orderKey(arr[j]);
                        if (kk > bk) { bk = kk; bc = (u32)cc; }
                    }
                }
            }
            u32 mk2 = __reduce_max_sync(FULLMASK, bk);
            u32 pc = (bk == mk2) ? (0x1000u - bc) : 0u;
            u32 ps = __reduce_max_sync(FULLMASK, pc);
            if (lane == ln) {
                sheads[ra] = mk2 ? packHead(mk2, ((u32)ra << 12) | (0x1000u - ps)) : 0ull;
                hptr[ra] = TCAND;
                if (rsA == ra) rsA = -1; else rsB = -1;
            }
        }
        __syncwarp(FULLMASK);

        // ---- refresh changed groups + lane tops ----
        if (ch1 || ch2) {
            int g1 = (r1 >> 3) & 3, g2 = (r2 >> 3) & 3;
            if (ch1) {
                u64 x1 = 0, x2 = 0, x3 = 0;
                const ulonglong2* gp = (const ulonglong2*)(sheads + base + g1 * 8);
                #pragma unroll
                for (int q = 0; q < 4; q++) { ulonglong2 hh = gp[q]; INS3(hh.x); INS3(hh.y); }
                sgt[(lane << 2) + g1] = x1;
                sgt[128 + (lane << 2) + g1] = x2;
                sgt[256 + (lane << 2) + g1] = x3;
            }
            if (ch2 && (!ch1 || g2 != g1)) {
                u64 x1 = 0, x2 = 0, x3 = 0;
                const ulonglong2* gp = (const ulonglong2*)(sheads + base + g2 * 8);
                #pragma unroll
                for (int q = 0; q < 4; q++) { ulonglong2 hh = gp[q]; INS3(hh.x); INS3(hh.y); }
                sgt[(lane << 2) + g2] = x1;
                sgt[128 + (lane << 2) + g2] = x2;
                sgt[256 + (lane << 2) + g2] = x3;
            }
            u64 x1 = 0, x2 = 0, x3 = 0;
            #pragma unroll
            for (int g = 0; g < 4; g++) {
                INS3(sgt[(lane << 2) + g]);
                INS3(sgt[128 + (lane << 2) + g]);
                INS3(sgt[256 + (lane << 2) + g]);
            }
            p1 = x1; p2 = x2; p3 = x3;
        }
    }
}

// ---------------- launch ---------------------------------------------------
extern "C" void kernel_launch(void* const* d_in, const int* in_sizes, int n_in,
                              void* d_out, int out_size) {
    const float* scores = (const float*)d_in[0];
    const int*   cont   = (const int*)d_in[1];
    const int*   prev   = (const int*)d_in[2];
    float* out = (float*)d_out;      // [0..1023] actions, [1024..] policy

    cudaFuncSetAttribute(k45_fused, cudaFuncAttributeMaxDynamicSharedMemorySize, DSMEM);

    k0_colhit<<<1, 1024>>>(cont, prev);
    k1_row<<<MM, 256>>>(scores, cont);
    k2_global<<<1, 1024>>>();
    k45_fused<<<513, 1024, DSMEM>>>(scores, cont, prev, out);
}